// round 12
// baseline (speedup 1.0000x reference)
#include <cuda_runtime.h>
#include <cuda_bf16.h>

// Problem constants (fixed by the reference)
#define PB   64
#define PT   512
#define PD   1024
#define NBLK 296     // contributor blocks (2 per SM on 148 SMs)
#define NFIN PB      // finalizer blocks (one per batch)

// Zero-invariant scratch: statically zero-initialized; finalizers restore
// zeros after consuming so every launch/replay sees zeros.
__device__ float    g_S  [PB * PD];   // unnormalized s[b,d]
__device__ float    g_YH [PB * PD];   // unnormalized y_hat[b,d]
__device__ unsigned g_cnt[2];         // [0]=contributor arrivals, [1]=finalizers done

// One vectorized no-return reduction: 1 LTS op per float4.
__device__ __forceinline__ void red_add_v4(float* p, float4 v)
{
    asm volatile("red.global.add.v4.f32 [%0], {%1, %2, %3, %4};"
                 :: "l"(p), "f"(v.x), "f"(v.y), "f"(v.z), "f"(v.w) : "memory");
}

__device__ __forceinline__ unsigned ld_acq(const unsigned* p)
{
    unsigned v;
    asm volatile("ld.acquire.gpu.global.u32 %0, [%1];" : "=r"(v) : "l"(p) : "memory");
    return v;
}

__device__ __forceinline__ void red_rel_add(unsigned* p)
{
    asm volatile("red.release.gpu.global.add.u32 [%0], %1;" :: "l"(p), "r"(1u) : "memory");
}

__device__ __forceinline__ void st_rel(unsigned* p, unsigned v)
{
    asm volatile("st.release.gpu.global.u32 [%0], %1;" :: "l"(p), "r"(v) : "memory");
}

// ---------------------------------------------------------------------------
// Single fused kernel. grid (NBLK + NFIN), block 256. One wave (360 blocks,
// 92K threads << residency), contributors scheduled first.
//   bid < NBLK : contributor. Prefix-sums len[] in smem (tiny), then handles
//       EXACTLY rows [bid*V/NBLK, (bid+1)*V/NBLK) of the global valid-row
//       list — per-block and per-SM work uniform by construction. Rows are
//       contiguous per batch run (4KB row stride, proven pattern); each
//       thread owns one float4 of the D=1024 row. Accumulators flush via
//       red.v4 at batch boundaries, then ONE release-inc of g_cnt[0].
//   bid >= NBLK : finalizer for b = bid-NBLK. Spins until g_cnt[0]==NBLK,
//       then L1-norm + outputs + scratch reset. Finalizer b==0 resets the
//       counters after all finalizers report done (graph-replay invariant).
// ---------------------------------------------------------------------------
__global__ void __launch_bounds__(256)
k_fused(const float* __restrict__ vs,
        const int*   __restrict__ len,
        const int*   __restrict__ word,
        const float* __restrict__ weights,
        float*       __restrict__ out)
{
    const int tid = threadIdx.x;
    const int bid = blockIdx.x;

    if (bid >= NBLK) {
        // ---------------- finalizer for batch b ----------------
        const int b = bid - NBLK;
        if (tid == 0) {
            while (ld_acq(&g_cnt[0]) < NBLK) __nanosleep(64);
        }
        __syncthreads();

        float4* sB = reinterpret_cast<float4*>(g_S  + (size_t)b * PD);
        float4* hB = reinterpret_cast<float4*>(g_YH + (size_t)b * PD);
        const float4 s4 = __ldcg(sB + tid);
        const float4 h4 = __ldcg(hB + tid);

        float part = fabsf(s4.x) + fabsf(s4.y) + fabsf(s4.z) + fabsf(s4.w);
#pragma unroll
        for (int o = 16; o > 0; o >>= 1)
            part += __shfl_xor_sync(0xFFFFFFFFu, part, o);

        __shared__ float sm[8];
        if ((tid & 31) == 0) sm[tid >> 5] = part;
        __syncthreads();
        float tot = 0.f;
#pragma unroll
        for (int i = 0; i < 8; ++i) tot += sm[i];

        const float r = rsqrtf(tot);

        reinterpret_cast<float4*>(out + (size_t)b * PD)[tid] =
            make_float4(s4.x * r, s4.y * r, s4.z * r, s4.w * r);
        reinterpret_cast<float4*>(out + (size_t)(PB + b) * PD)[tid] = h4;

        const float4 z = make_float4(0.f, 0.f, 0.f, 0.f);
        sB[tid] = z;            // restore zero-invariant
        hB[tid] = z;

        __syncthreads();
        if (tid == 0) {
            red_rel_add(&g_cnt[1]);
            if (b == 0) {       // resetter: after ALL finalizers are done
                while (ld_acq(&g_cnt[1]) < NFIN) __nanosleep(32);
                st_rel(&g_cnt[0], 0u);
                st_rel(&g_cnt[1], 0u);
            }
        }
        return;
    }

    // ---------------- contributor ----------------
    // Inclusive prefix sum of len[0..63] in shared memory (Hillis-Steele).
    __shared__ int pre[PB];
    if (tid < PB) pre[tid] = len[tid];
    __syncthreads();
#pragma unroll
    for (int off = 1; off < PB; off <<= 1) {
        int v = (tid < PB && tid >= off) ? pre[tid - off] : 0;
        __syncthreads();
        if (tid < PB) pre[tid] += v;
        __syncthreads();
    }
    const int V = pre[PB - 1];   // total valid rows (>= PB since len >= 1)

    const int lo = (int)(((long long)bid       * V) / NBLK);
    const int hi = (int)(((long long)(bid + 1) * V) / NBLK);

    if (lo < hi) {
        // binary search: first b with pre[b] > lo
        int blo = 0, bhi = PB - 1;
        while (blo < bhi) {
            const int mid = (blo + bhi) >> 1;
            if (pre[mid] > lo) bhi = mid; else blo = mid + 1;
        }
        int b    = blo;
        int base = (b == 0) ? 0 : pre[b - 1];
        int r    = lo;

        while (r < hi) {
            const int bend = pre[b];
            const int cnt  = min(hi, bend) - r;   // contiguous rows in batch b
            const int t    = r - base;

            const int wbase = b * PT + t;
            const float4* __restrict__ p =
                reinterpret_cast<const float4*>(vs + ((size_t)b * PT + t) * PD) + tid;

            float4 acc  = make_float4(0.f, 0.f, 0.f, 0.f);
            float4 accw = make_float4(0.f, 0.f, 0.f, 0.f);

#pragma unroll 4
            for (int i = 0; i < cnt; ++i) {
                const float4 v = p[(size_t)i * (PD / 4)];
                const float  w = weights[word[wbase + i]];   // uniform broadcast
                acc.x  += v.x;      acc.y  += v.y;      acc.z  += v.z;      acc.w  += v.w;
                accw.x += w * v.x;  accw.y += w * v.y;  accw.z += w * v.z;  accw.w += w * v.w;
            }

            red_add_v4(g_S  + (size_t)b * PD + tid * 4, acc);
            red_add_v4(g_YH + (size_t)b * PD + tid * 4, accw);

            r   += cnt;
            base = bend;
            ++b;
        }
    }

    // Arrival: CTA barrier, then one gpu-scope release increment (cumulativity
    // makes all threads' reductions visible to the finalizers' acquires).
    __syncthreads();
    if (tid == 0) red_rel_add(&g_cnt[0]);
}

// ---------------------------------------------------------------------------
// Entry point: one kernel, one launch.
// ---------------------------------------------------------------------------
extern "C" void kernel_launch(void* const* d_in, const int* in_sizes, int n_in,
                              void* d_out, int out_size)
{
    const float* vs      = (const float*)d_in[0];  // [B,T,D] f32
    const int*   len     = (const int*)  d_in[1];  // [B]
    const int*   word    = (const int*)  d_in[2];  // [B,T]
    const float* weights = (const float*)d_in[3];  // [VOCAB]

    float* out = (float*)d_out;  // y at [0, B*D), y_hat at [B*D, 2*B*D)

    k_fused<<<NBLK + NFIN, 256>>>(vs, len, word, weights, out);
}

// round 14
// speedup vs baseline: 1.3110x; 1.3110x over previous
#include <cuda_runtime.h>
#include <cuda_bf16.h>

// Problem constants (fixed by the reference)
#define PB    64
#define PT    512
#define PD    1024
#define CHUNK 16                     // rows per work item
#define NCHNK (PT / CHUNK)           // 32 chunks per (b, d-half)
#define NITEMS (PB * 2 * NCHNK)      // 4096 items: (b, dhalf, chunk)
#define NCONTRIB (2 * NCHNK)         // 64 items per b
#define NBLKW 1184                   // persistent worker blocks (8 per SM)

// Zero-invariant scratch: statically zero-initialized; the inline finalizer
// restores zeros after consuming, so every launch/replay sees zeros.
__device__ float    g_S  [PB * PD];  // unnormalized s[b,d]
__device__ float    g_YH [PB * PD];  // unnormalized y_hat[b,d]
__device__ unsigned g_cnt[PB];       // per-b retired-item counters
__device__ unsigned g_ticket;        // global work ticket
__device__ unsigned g_done;          // blocks that exhausted the queue

// One vectorized no-return reduction: 1 LTS op per float4.
__device__ __forceinline__ void red_add_v4(float* p, float4 v)
{
    asm volatile("red.global.add.v4.f32 [%0], {%1, %2, %3, %4};"
                 :: "l"(p), "f"(v.x), "f"(v.y), "f"(v.z), "f"(v.w) : "memory");
}

// acq_rel RMW: releases this block's prior writes, acquires all prior
// releases on the same counter (so old==NCONTRIB-1 implies full visibility).
__device__ __forceinline__ unsigned atom_add_acqrel(unsigned* p)
{
    unsigned old;
    asm volatile("atom.add.acq_rel.gpu.global.u32 %0, [%1], %2;"
                 : "=r"(old) : "l"(p), "r"(1u) : "memory");
    return old;
}

__device__ __forceinline__ void st_rel(unsigned* p, unsigned v)
{
    asm volatile("st.release.gpu.global.u32 [%0], %1;" :: "l"(p), "r"(v) : "memory");
}

// ---------------------------------------------------------------------------
// Single persistent kernel. grid NBLKW, block 128. No spins anywhere.
// Each block loops: pop item -> (skip if masked | stream 16 contiguous rows
// of one d-half, R7-shaped) -> retire item on g_cnt[b]; the block retiring
// the 64th item of b finalizes b inline (norm + outputs + scratch reset).
// After the queue drains, the last block out resets ticket/done counters.
// ---------------------------------------------------------------------------
__global__ void __launch_bounds__(128)
k_fused(const float* __restrict__ vs,
        const int*   __restrict__ len,
        const int*   __restrict__ word,
        const float* __restrict__ weights,
        float*       __restrict__ out)
{
    const int tid = threadIdx.x;
    __shared__ unsigned s_id;
    __shared__ int      s_fin;
    __shared__ float    sm[4];

    for (;;) {
        if (tid == 0) s_id = atomicAdd(&g_ticket, 1u);
        __syncthreads();
        const unsigned id = s_id;
        if (id >= NITEMS) break;                   // uniform exit

        const int b     = id >> 6;                 // 64 items per b
        const int dhalf = (id >> 5) & 1;
        const int t0    = (id & (NCHNK - 1)) * CHUNK;
        const int L     = __ldg(len + b);

        if (t0 < L) {
            const int n = min(L - t0, CHUNK);

            // Warp-wide weight gather (R7 pattern): lane j holds
            // weights[word[b, t0 + (j&15)]]; broadcast via shfl in the loop.
            const int   lane  = tid & 31;
            const float wlane = weights[word[b * PT + t0 + (lane & (CHUNK - 1))]];

            const int d0 = dhalf * 512 + tid * 4;

            const float4* __restrict__ p =
                reinterpret_cast<const float4*>(vs + ((size_t)b * PT + t0) * PD + d0);
            const size_t stride = PD / 4;          // next row: 4KB away

            float4 acc  = make_float4(0.f, 0.f, 0.f, 0.f);
            float4 accw = make_float4(0.f, 0.f, 0.f, 0.f);

#pragma unroll 4
            for (int i = 0; i < n; ++i) {
                const float4 v = p[(size_t)i * stride];
                const float  w = __shfl_sync(0xFFFFFFFFu, wlane, i);
                acc.x  += v.x;      acc.y  += v.y;      acc.z  += v.z;      acc.w  += v.w;
                accw.x += w * v.x;  accw.y += w * v.y;  accw.z += w * v.z;  accw.w += w * v.w;
            }

            red_add_v4(g_S  + (size_t)b * PD + d0, acc);
            red_add_v4(g_YH + (size_t)b * PD + d0, accw);
        }

        // Retire the item. CTA barrier gives happens-before from all threads'
        // reds to thread 0's acq_rel RMW; the RMW that observes old==63 has
        // acquired every earlier release on this counter.
        __syncthreads();
        if (tid == 0)
            s_fin = (atom_add_acqrel(&g_cnt[b]) == NCONTRIB - 1);
        __syncthreads();

        if (s_fin) {
            // ---------------- inline finalizer for batch b ----------------
            float4* sB = reinterpret_cast<float4*>(g_S  + (size_t)b * PD);
            float4* hB = reinterpret_cast<float4*>(g_YH + (size_t)b * PD);

            float4 s[2], h[2];
#pragma unroll
            for (int j = 0; j < 2; ++j) {
                s[j] = __ldcg(sB + tid + 128 * j);
                h[j] = __ldcg(hB + tid + 128 * j);
            }

            float part = 0.f;
#pragma unroll
            for (int j = 0; j < 2; ++j)
                part += fabsf(s[j].x) + fabsf(s[j].y) + fabsf(s[j].z) + fabsf(s[j].w);

#pragma unroll
            for (int o = 16; o > 0; o >>= 1)
                part += __shfl_xor_sync(0xFFFFFFFFu, part, o);

            if ((tid & 31) == 0) sm[tid >> 5] = part;
            __syncthreads();
            const float tot = sm[0] + sm[1] + sm[2] + sm[3];
            const float r   = rsqrtf(tot);

            float4* outY = reinterpret_cast<float4*>(out + (size_t)b * PD);
            float4* outH = reinterpret_cast<float4*>(out + (size_t)(PB + b) * PD);
            const float4 z = make_float4(0.f, 0.f, 0.f, 0.f);
#pragma unroll
            for (int j = 0; j < 2; ++j) {
                outY[tid + 128 * j] =
                    make_float4(s[j].x * r, s[j].y * r, s[j].z * r, s[j].w * r);
                outH[tid + 128 * j] = h[j];
                sB[tid + 128 * j] = z;     // restore zero-invariant
                hB[tid + 128 * j] = z;
            }
            if (tid == 0) st_rel(&g_cnt[b], 0u);   // ready for next replay
            __syncthreads();               // protect sm[] before next item reuses it
        }
    }

    // Queue drained. Last block out resets the ticket for the next replay;
    // guaranteed no block pops after this (each block increments g_done only
    // after its final failing pop).
    if (tid == 0) {
        if (atomicAdd(&g_done, 1u) == NBLKW - 1) {
            st_rel(&g_ticket, 0u);
            st_rel(&g_done,   0u);
        }
    }
}

// ---------------------------------------------------------------------------
// Entry point: one kernel, one launch.
// ---------------------------------------------------------------------------
extern "C" void kernel_launch(void* const* d_in, const int* in_sizes, int n_in,
                              void* d_out, int out_size)
{
    const float* vs      = (const float*)d_in[0];  // [B,T,D] f32
    const int*   len     = (const int*)  d_in[1];  // [B]
    const int*   word    = (const int*)  d_in[2];  // [B,T]
    const float* weights = (const float*)d_in[3];  // [VOCAB]

    float* out = (float*)d_out;  // y at [0, B*D), y_hat at [B*D, 2*B*D)

    k_fused<<<NBLKW, 128>>>(vs, len, word, weights, out);
}

// round 15
// speedup vs baseline: 1.7384x; 1.3259x over previous
#include <cuda_runtime.h>
#include <cuda_bf16.h>

// Problem constants (fixed by the reference)
#define PB 64
#define PT 512
#define PD 1024
#define TS 16                 // t-chunks per (b, d-half)
#define TT (PT / TS)          // 32 rows per contributor block (== warp size)
#define NCONTRIB (2 * TS)     // 32 contributor blocks per b

// Occupancy throttle: 24KB static smem -> ~9 blocks/SM resident, leaving
// ~850 of 2176 blocks queued so the HW scheduler backfills SMs as masked
// blocks retire (greedy list scheduling; bounds the straggler tail by ~one
// block instead of the max-loaded SM).
#define SMEM_PAD_FLOATS (6144)   // 24 KB

// Zero-invariant scratch: statically zero-initialized at module load; the
// per-b finalizer restores zeros after consuming, so every kernel_launch call
// (correctness run + each graph replay) sees zeros.
__device__ float    g_S  [PB * PD];  // unnormalized s[b,d]
__device__ float    g_YH [PB * PD];  // unnormalized y_hat[b,d]
__device__ unsigned g_cnt[PB];       // per-b arrival counters

// One vectorized no-return reduction: 1 LTS op per float4.
__device__ __forceinline__ void red_add_v4(float* p, float4 v)
{
    asm volatile("red.global.add.v4.f32 [%0], {%1, %2, %3, %4};"
                 :: "l"(p), "f"(v.x), "f"(v.y), "f"(v.z), "f"(v.w) : "memory");
}

// ---------------------------------------------------------------------------
// Single fused kernel (R7 structure, proven). grid (2, TS+1, PB), block 128.
//   by <  TS : contributor — contiguous 32-row t-chunk [32*by, 32*by+32)∩[0,L),
//              4KB row stride, unroll-4, lane-gather + shfl weights.
//              Fully-masked chunks exit before any global load (slot refills
//              from the queue). Partials -> red.v4, then ONE release-inc of
//              g_cnt[b] by thread 0.
//   by == TS, bx == 0 : finalizer for b — acquire-spin until all 32
//              contributors arrived, then L1-norm + outputs + scratch reset.
//              (bid ordering: contributors of b precede finalizer b, so the
//              spin always terminates; no deadlock under the occupancy cap.)
// ---------------------------------------------------------------------------
__global__ void __launch_bounds__(128)
k_fused(const float* __restrict__ vs,
        const int*   __restrict__ len,
        const int*   __restrict__ word,
        const float* __restrict__ weights,
        float*       __restrict__ out)
{
    // Occupancy throttle + finalizer reduction buffer (only [0..3] used).
    __shared__ float sm[SMEM_PAD_FLOATS];

    const int b = blockIdx.z;

    if (blockIdx.y == TS) {
        if (blockIdx.x != 0) return;
        // ---------------- finalizer for batch b ----------------
        unsigned* cnt = &g_cnt[b];
        if (threadIdx.x == 0) {
            unsigned v;
            for (;;) {
                asm volatile("ld.acquire.gpu.global.u32 %0, [%1];"
                             : "=r"(v) : "l"(cnt) : "memory");
                if (v >= NCONTRIB) break;
                __nanosleep(64);
            }
            *cnt = 0;  // reset for next replay (kernel-boundary ordering)
        }
        __syncthreads();

        const int tid = threadIdx.x;
        float4* sB = reinterpret_cast<float4*>(g_S  + (size_t)b * PD);
        float4* hB = reinterpret_cast<float4*>(g_YH + (size_t)b * PD);

        float4 s[2], h[2];
#pragma unroll
        for (int j = 0; j < 2; ++j) {
            s[j] = __ldcg(sB + tid + 128 * j);
            h[j] = __ldcg(hB + tid + 128 * j);
        }

        float part = 0.f;
#pragma unroll
        for (int j = 0; j < 2; ++j)
            part += fabsf(s[j].x) + fabsf(s[j].y) + fabsf(s[j].z) + fabsf(s[j].w);

#pragma unroll
        for (int o = 16; o > 0; o >>= 1)
            part += __shfl_xor_sync(0xFFFFFFFFu, part, o);

        if ((tid & 31) == 0) sm[tid >> 5] = part;
        __syncthreads();
        const float tot = sm[0] + sm[1] + sm[2] + sm[3];
        const float r   = rsqrtf(tot);

        float4* outY = reinterpret_cast<float4*>(out + (size_t)b * PD);
        float4* outH = reinterpret_cast<float4*>(out + (size_t)(PB + b) * PD);
        const float4 z = make_float4(0.f, 0.f, 0.f, 0.f);
#pragma unroll
        for (int j = 0; j < 2; ++j) {
            outY[tid + 128 * j] =
                make_float4(s[j].x * r, s[j].y * r, s[j].z * r, s[j].w * r);
            outH[tid + 128 * j] = h[j];
            sB[tid + 128 * j] = z;   // restore zero-invariant
            hB[tid + 128 * j] = z;
        }
        return;
    }

    // ---------------- contributor ----------------
    const int L  = __ldg(len + b);
    const int t0 = blockIdx.y * TT;

    if (t0 < L) {
        const int n = min(L - t0, TT);

        // Warp-wide weight gather: lane j holds weights[word[b, t0+j]]
        // (indices always in-bounds; values beyond n unused).
        const int   lane  = threadIdx.x & 31;
        const float wlane = weights[word[b * PT + t0 + lane]];

        const int d0 = blockIdx.x * 512 + threadIdx.x * 4;

        const float4* __restrict__ p =
            reinterpret_cast<const float4*>(vs + ((size_t)b * PT + t0) * PD + d0);
        const size_t stride = PD / 4;

        float4 acc  = make_float4(0.f, 0.f, 0.f, 0.f);
        float4 accw = make_float4(0.f, 0.f, 0.f, 0.f);

#pragma unroll 4
        for (int i = 0; i < n; ++i) {
            const float4 v = p[(size_t)i * stride];
            const float  w = __shfl_sync(0xFFFFFFFFu, wlane, i);
            acc.x  += v.x;      acc.y  += v.y;      acc.z  += v.z;      acc.w  += v.w;
            accw.x += w * v.x;  accw.y += w * v.y;  accw.z += w * v.z;  accw.w += w * v.w;
        }

        red_add_v4(g_S  + (size_t)b * PD + d0, acc);
        red_add_v4(g_YH + (size_t)b * PD + d0, accw);
    }

    // Arrival: CTA barrier (happens-before from all threads to thread 0),
    // then a single gpu-scope release increment. Cumulativity makes every
    // thread's reductions visible to the finalizer's acquire.
    __syncthreads();
    if (threadIdx.x == 0) {
        asm volatile("red.release.gpu.global.add.u32 [%0], %1;"
                     :: "l"(&g_cnt[b]), "r"(1u) : "memory");
    }
}

// ---------------------------------------------------------------------------
// Entry point: one kernel, one launch.
// ---------------------------------------------------------------------------
extern "C" void kernel_launch(void* const* d_in, const int* in_sizes, int n_in,
                              void* d_out, int out_size)
{
    const float* vs      = (const float*)d_in[0];  // [B,T,D] f32
    const int*   len     = (const int*)  d_in[1];  // [B]
    const int*   word    = (const int*)  d_in[2];  // [B,T]
    const float* weights = (const float*)d_in[3];  // [VOCAB]

    float* out = (float*)d_out;  // y at [0, B*D), y_hat at [B*D, 2*B*D)

    k_fused<<<dim3(2, TS + 1, PB), 128>>>(vs, len, word, weights, out);
}

// round 16
// speedup vs baseline: 1.7618x; 1.0135x over previous
#include <cuda_runtime.h>
#include <cuda_bf16.h>

// Problem constants (fixed by the reference)
#define PB 64
#define PT 512
#define PD 1024
#define TS 16                 // t-chunks per (b, d-half)
#define TT (PT / TS)          // 32 rows per contributor block (== warp size)
#define NCONTRIB (2 * TS)     // 32 contributor blocks per b
#define NCB (PB * 2 * TS)     // 2048 contributor blocks total

// Occupancy throttle: 24KB static smem -> ~9 blocks/SM resident; the rest
// queue, and the HW scheduler backfills slots as blocks retire (greedy list
// scheduling). Combined with LPT launch order below, the makespan tightens
// to ~mean SM load + one block.
#define SMEM_PAD_FLOATS (6144)   // 24 KB

// Zero-invariant scratch: statically zero-initialized at module load; the
// per-b finalizer restores zeros after consuming, so every kernel_launch call
// (correctness run + each graph replay) sees zeros.
__device__ float    g_S  [PB * PD];  // unnormalized s[b,d]
__device__ float    g_YH [PB * PD];  // unnormalized y_hat[b,d]
__device__ unsigned g_cnt[PB];       // per-b arrival counters

// One vectorized no-return reduction: 1 LTS op per float4.
__device__ __forceinline__ void red_add_v4(float* p, float4 v)
{
    asm volatile("red.global.add.v4.f32 [%0], {%1, %2, %3, %4};"
                 :: "l"(p), "f"(v.x), "f"(v.y), "f"(v.z), "f"(v.w) : "memory");
}

// ---------------------------------------------------------------------------
// Single fused kernel, 1D grid of NCB+PB blocks, LPT launch order:
//   bid < NCB : contributor. tc = bid>>7 ascending across the launch, so
//       always-full chunks (t0=0) launch first and mostly-masked chunks
//       (t0 large) last — longest-work-first into the backfill queue.
//       Chunk work identical to R7/R15: contiguous 32 rows @4KB stride,
//       lane-gather+shfl weights, unroll-4, red.v4 partials, one
//       release-inc of g_cnt[b].
//   bid >= NCB : finalizer for b = bid-NCB, launched after ALL contributors
//       (no early-resident spinners). Acquire-spin until 32 arrivals, then
//       L1-norm + outputs + scratch reset.
// ---------------------------------------------------------------------------
__global__ void __launch_bounds__(128)
k_fused(const float* __restrict__ vs,
        const int*   __restrict__ len,
        const int*   __restrict__ word,
        const float* __restrict__ weights,
        float*       __restrict__ out)
{
    // Occupancy throttle + finalizer reduction buffer (only [0..3] used).
    __shared__ float sm[SMEM_PAD_FLOATS];

    const int bid = blockIdx.x;
    const int tid = threadIdx.x;

    if (bid >= NCB) {
        // ---------------- finalizer for batch b ----------------
        const int b = bid - NCB;
        unsigned* cnt = &g_cnt[b];
        if (tid == 0) {
            unsigned v;
            for (;;) {
                asm volatile("ld.acquire.gpu.global.u32 %0, [%1];"
                             : "=r"(v) : "l"(cnt) : "memory");
                if (v >= NCONTRIB) break;
                __nanosleep(64);
            }
            *cnt = 0;  // reset for next replay (kernel-boundary ordering)
        }
        __syncthreads();

        float4* sB = reinterpret_cast<float4*>(g_S  + (size_t)b * PD);
        float4* hB = reinterpret_cast<float4*>(g_YH + (size_t)b * PD);

        float4 s[2], h[2];
#pragma unroll
        for (int j = 0; j < 2; ++j) {
            s[j] = __ldcg(sB + tid + 128 * j);
            h[j] = __ldcg(hB + tid + 128 * j);
        }

        float part = 0.f;
#pragma unroll
        for (int j = 0; j < 2; ++j)
            part += fabsf(s[j].x) + fabsf(s[j].y) + fabsf(s[j].z) + fabsf(s[j].w);

#pragma unroll
        for (int o = 16; o > 0; o >>= 1)
            part += __shfl_xor_sync(0xFFFFFFFFu, part, o);

        if ((tid & 31) == 0) sm[tid >> 5] = part;
        __syncthreads();
        const float tot = sm[0] + sm[1] + sm[2] + sm[3];
        const float r   = rsqrtf(tot);

        float4* outY = reinterpret_cast<float4*>(out + (size_t)b * PD);
        float4* outH = reinterpret_cast<float4*>(out + (size_t)(PB + b) * PD);
        const float4 z = make_float4(0.f, 0.f, 0.f, 0.f);
#pragma unroll
        for (int j = 0; j < 2; ++j) {
            outY[tid + 128 * j] =
                make_float4(s[j].x * r, s[j].y * r, s[j].z * r, s[j].w * r);
            outH[tid + 128 * j] = h[j];
            sB[tid + 128 * j] = z;   // restore zero-invariant
            hB[tid + 128 * j] = z;
        }
        return;
    }

    // ---------------- contributor ----------------
    // LPT index mapping: t-chunk varies slowest across the launch order.
    const int tc    = bid >> 7;          // 0..15  (t0 ascending => full chunks first)
    const int b     = (bid >> 1) & 63;   // batch
    const int dhalf = bid & 1;           // d-half
    const int t0    = tc * TT;

    const int L = __ldg(len + b);

    if (t0 < L) {
        const int n = min(L - t0, TT);

        // Warp-wide weight gather: lane j holds weights[word[b, t0+j]]
        // (indices always in-bounds; values beyond n unused).
        const int   lane  = tid & 31;
        const float wlane = weights[word[b * PT + t0 + lane]];

        const int d0 = dhalf * 512 + tid * 4;

        const float4* __restrict__ p =
            reinterpret_cast<const float4*>(vs + ((size_t)b * PT + t0) * PD + d0);
        const size_t stride = PD / 4;

        float4 acc  = make_float4(0.f, 0.f, 0.f, 0.f);
        float4 accw = make_float4(0.f, 0.f, 0.f, 0.f);

#pragma unroll 4
        for (int i = 0; i < n; ++i) {
            const float4 v = p[(size_t)i * stride];
            const float  w = __shfl_sync(0xFFFFFFFFu, wlane, i);
            acc.x  += v.x;      acc.y  += v.y;      acc.z  += v.z;      acc.w  += v.w;
            accw.x += w * v.x;  accw.y += w * v.y;  accw.z += w * v.z;  accw.w += w * v.w;
        }

        red_add_v4(g_S  + (size_t)b * PD + d0, acc);
        red_add_v4(g_YH + (size_t)b * PD + d0, accw);
    }

    // Arrival: CTA barrier (happens-before from all threads to thread 0),
    // then a single gpu-scope release increment. Cumulativity makes every
    // thread's reductions visible to the finalizer's acquire.
    __syncthreads();
    if (tid == 0) {
        asm volatile("red.release.gpu.global.add.u32 [%0], %1;"
                     :: "l"(&g_cnt[b]), "r"(1u) : "memory");
    }
}

// ---------------------------------------------------------------------------
// Entry point: one kernel, one launch.
// ---------------------------------------------------------------------------
extern "C" void kernel_launch(void* const* d_in, const int* in_sizes, int n_in,
                              void* d_out, int out_size)
{
    const float* vs      = (const float*)d_in[0];  // [B,T,D] f32
    const int*   len     = (const int*)  d_in[1];  // [B]
    const int*   word    = (const int*)  d_in[2];  // [B,T]
    const float* weights = (const float*)d_in[3];  // [VOCAB]

    float* out = (float*)d_out;  // y at [0, B*D), y_hat at [B*D, 2*B*D)

    k_fused<<<NCB + PB, 128>>>(vs, len, word, weights, out);
}

// round 17
// speedup vs baseline: 1.9600x; 1.1125x over previous
#include <cuda_runtime.h>
#include <cuda_bf16.h>

// Problem constants (fixed by the reference)
#define PB 64
#define PT 512
#define PD 1024
#define TS 16                 // t-chunks per (b, d-half)
#define TT (PT / TS)          // 32 rows per contributor block (== warp size)
#define NCONTRIB (2 * TS)     // 32 contributor blocks per b
#define NCB (PB * 2 * TS)     // 2048 contributor blocks total

// Occupancy throttle: 24KB static smem -> ~9 blocks/SM resident; the rest
// queue, and the HW scheduler backfills slots as blocks retire (greedy list
// scheduling). Combined with LPT launch order, makespan ~ mean + one block.
#define SMEM_PAD_FLOATS (6144)   // 24 KB

// Zero-invariant scratch: statically zero-initialized at module load; the
// per-b finalizer restores zeros after consuming, so every kernel_launch call
// (correctness run + each graph replay) sees zeros.
__device__ float    g_S  [PB * PD];  // unnormalized s[b,d]
__device__ float    g_YH [PB * PD];  // unnormalized y_hat[b,d]
__device__ unsigned g_cnt[PB];       // per-b arrival counters

// One vectorized no-return reduction: 1 LTS op per float4.
__device__ __forceinline__ void red_add_v4(float* p, float4 v)
{
    asm volatile("red.global.add.v4.f32 [%0], {%1, %2, %3, %4};"
                 :: "l"(p), "f"(v.x), "f"(v.y), "f"(v.z), "f"(v.w) : "memory");
}

// ---------------------------------------------------------------------------
// Single fused kernel, 1D grid of NCB+PB blocks, LPT launch order:
//   bid < NCB : contributor. tc = bid>>7 ascending, so always-full chunks
//       launch first, mostly-masked chunks last (longest-work-first into the
//       backfill queue). Contiguous 32 rows @4KB stride, lane-gather+shfl
//       weights, UNROLL-8 (16KB/block in flight -> single-block drain rate
//       ~2x R16, halving the end-of-kernel tail), red.v4 partials, one
//       release-inc of g_cnt[b].
//   bid >= NCB : finalizer for b = bid-NCB, launched after ALL contributors.
//       Acquire-spin until 32 arrivals, then L1-norm + outputs + reset.
// ---------------------------------------------------------------------------
__global__ void __launch_bounds__(128)
k_fused(const float* __restrict__ vs,
        const int*   __restrict__ len,
        const int*   __restrict__ word,
        const float* __restrict__ weights,
        float*       __restrict__ out)
{
    // Occupancy throttle + finalizer reduction buffer (only [0..3] used).
    __shared__ float sm[SMEM_PAD_FLOATS];

    const int bid = blockIdx.x;
    const int tid = threadIdx.x;

    if (bid >= NCB) {
        // ---------------- finalizer for batch b ----------------
        const int b = bid - NCB;
        unsigned* cnt = &g_cnt[b];
        if (tid == 0) {
            unsigned v;
            for (;;) {
                asm volatile("ld.acquire.gpu.global.u32 %0, [%1];"
                             : "=r"(v) : "l"(cnt) : "memory");
                if (v >= NCONTRIB) break;
                __nanosleep(64);
            }
            *cnt = 0;  // reset for next replay (kernel-boundary ordering)
        }
        __syncthreads();

        float4* sB = reinterpret_cast<float4*>(g_S  + (size_t)b * PD);
        float4* hB = reinterpret_cast<float4*>(g_YH + (size_t)b * PD);

        float4 s[2], h[2];
#pragma unroll
        for (int j = 0; j < 2; ++j) {
            s[j] = __ldcg(sB + tid + 128 * j);
            h[j] = __ldcg(hB + tid + 128 * j);
        }

        float part = 0.f;
#pragma unroll
        for (int j = 0; j < 2; ++j)
            part += fabsf(s[j].x) + fabsf(s[j].y) + fabsf(s[j].z) + fabsf(s[j].w);

#pragma unroll
        for (int o = 16; o > 0; o >>= 1)
            part += __shfl_xor_sync(0xFFFFFFFFu, part, o);

        if ((tid & 31) == 0) sm[tid >> 5] = part;
        __syncthreads();
        const float tot = sm[0] + sm[1] + sm[2] + sm[3];
        const float r   = rsqrtf(tot);

        float4* outY = reinterpret_cast<float4*>(out + (size_t)b * PD);
        float4* outH = reinterpret_cast<float4*>(out + (size_t)(PB + b) * PD);
        const float4 z = make_float4(0.f, 0.f, 0.f, 0.f);
#pragma unroll
        for (int j = 0; j < 2; ++j) {
            outY[tid + 128 * j] =
                make_float4(s[j].x * r, s[j].y * r, s[j].z * r, s[j].w * r);
            outH[tid + 128 * j] = h[j];
            sB[tid + 128 * j] = z;   // restore zero-invariant
            hB[tid + 128 * j] = z;
        }
        return;
    }

    // ---------------- contributor ----------------
    // LPT index mapping: t-chunk varies slowest across the launch order.
    const int tc    = bid >> 7;          // 0..15  (t0 ascending => full chunks first)
    const int b     = (bid >> 1) & 63;   // batch
    const int dhalf = bid & 1;           // d-half
    const int t0    = tc * TT;

    const int L = __ldg(len + b);

    if (t0 < L) {
        const int n = min(L - t0, TT);

        // Warp-wide weight gather: lane j holds weights[word[b, t0+j]]
        // (indices always in-bounds; values beyond n unused).
        const int   lane  = tid & 31;
        const float wlane = weights[word[b * PT + t0 + lane]];

        const int d0 = dhalf * 512 + tid * 4;

        const float4* __restrict__ p =
            reinterpret_cast<const float4*>(vs + ((size_t)b * PT + t0) * PD + d0);
        const size_t stride = PD / 4;

        float4 acc  = make_float4(0.f, 0.f, 0.f, 0.f);
        float4 accw = make_float4(0.f, 0.f, 0.f, 0.f);

#pragma unroll 8
        for (int i = 0; i < n; ++i) {
            const float4 v = p[(size_t)i * stride];
            const float  w = __shfl_sync(0xFFFFFFFFu, wlane, i);
            acc.x  += v.x;      acc.y  += v.y;      acc.z  += v.z;      acc.w  += v.w;
            accw.x += w * v.x;  accw.y += w * v.y;  accw.z += w * v.z;  accw.w += w * v.w;
        }

        red_add_v4(g_S  + (size_t)b * PD + d0, acc);
        red_add_v4(g_YH + (size_t)b * PD + d0, accw);
    }

    // Arrival: CTA barrier (happens-before from all threads to thread 0),
    // then a single gpu-scope release increment. Cumulativity makes every
    // thread's reductions visible to the finalizer's acquire.
    __syncthreads();
    if (tid == 0) {
        asm volatile("red.release.gpu.global.add.u32 [%0], %1;"
                     :: "l"(&g_cnt[b]), "r"(1u) : "memory");
    }
}

// ---------------------------------------------------------------------------
// Entry point: one kernel, one launch.
// ---------------------------------------------------------------------------
extern "C" void kernel_launch(void* const* d_in, const int* in_sizes, int n_in,
                              void* d_out, int out_size)
{
    const float* vs      = (const float*)d_in[0];  // [B,T,D] f32
    const int*   len     = (const int*)  d_in[1];  // [B]
    const int*   word    = (const int*)  d_in[2];  // [B,T]
    const float* weights = (const float*)d_in[3];  // [VOCAB]

    float* out = (float*)d_out;  // y at [0, B*D), y_hat at [B*D, 2*B*D)

    k_fused<<<NCB + PB, 128>>>(vs, len, word, weights, out);
}